// round 12
// baseline (speedup 1.0000x reference)
#include <cuda_runtime.h>
#include <cuda_bf16.h>
#include <cuda_fp16.h>
#include <math.h>
#include <stdint.h>

// Problem constants
#define SEQ 2048
#define DM  1024
#define NH  16
#define DKH 64

// ===========================================================================
// Portable PTX helpers (base compute_103 target)
// ===========================================================================
__device__ __forceinline__ uint32_t smem_to_u32(const void* smem_ptr) {
    uint32_t addr;
    asm("{ .reg .u64 tmp; cvta.to.shared.u64 tmp, %1; cvt.u32.u64 %0, tmp; }"
        : "=r"(addr) : "l"(smem_ptr));
    return addr;
}

#define LDSM_X4(r0, r1, r2, r3, addr) \
    asm volatile("ldmatrix.sync.aligned.m8n8.x4.shared.b16 {%0,%1,%2,%3}, [%4];" \
        : "=r"(r0), "=r"(r1), "=r"(r2), "=r"(r3) : "r"(addr))

#define LDSM_X4T(r0, r1, r2, r3, addr) \
    asm volatile("ldmatrix.sync.aligned.m8n8.x4.trans.shared.b16 {%0,%1,%2,%3}, [%4];" \
        : "=r"(r0), "=r"(r1), "=r"(r2), "=r"(r3) : "r"(addr))

#define MMA16816(c, a, b0, b1) \
    asm volatile("mma.sync.aligned.m16n8k16.row.col.f32.bf16.bf16.f32 " \
        "{%0,%1,%2,%3},{%4,%5,%6,%7},{%8,%9},{%0,%1,%2,%3};" \
        : "+f"((c)[0]), "+f"((c)[1]), "+f"((c)[2]), "+f"((c)[3]) \
        : "r"((a)[0]), "r"((a)[1]), "r"((a)[2]), "r"((a)[3]), "r"(b0), "r"(b1))

#define MMA16816H(c, a, b0, b1) \
    asm volatile("mma.sync.aligned.m16n8k16.row.col.f32.f16.f16.f32 " \
        "{%0,%1,%2,%3},{%4,%5,%6,%7},{%8,%9},{%0,%1,%2,%3};" \
        : "+f"((c)[0]), "+f"((c)[1]), "+f"((c)[2]), "+f"((c)[3]) \
        : "r"((a)[0]), "r"((a)[1]), "r"((a)[2]), "r"((a)[3]), "r"(b0), "r"(b1))

#define CP_ASYNC16(smaddr, gptr) \
    asm volatile("cp.async.cg.shared.global [%0], [%1], 16;" \
        :: "r"(smaddr), "l"(gptr))
#define CP_COMMIT() asm volatile("cp.async.commit_group;" ::: "memory")
#define CP_WAIT0()  asm volatile("cp.async.wait_group 0;" ::: "memory")
#define CP_WAIT1()  asm volatile("cp.async.wait_group 1;" ::: "memory")

__device__ __forceinline__ void split2(float x, __nv_bfloat16& h, __nv_bfloat16& l) {
    h = __float2bfloat16(x);
    l = __float2bfloat16(x - __bfloat162float(h));
}
__device__ __forceinline__ void split2h(float x, __half& h, __half& l) {
    h = __float2half_rn(x);
    l = __float2half_rn(x - __half2float(h));
}

// ===========================================================================
// Scratch (device globals)
// ===========================================================================
__device__ float g_Q[SEQ * DM];
__device__ float g_K[SEQ * DM];
__device__ float g_V[SEQ * DM];      // reused: fp16 split of projected V (hi|lo)
__device__ float g_OUT[SEQ * DM];
__device__ float g_ATTN[(size_t)NH * SEQ * SEQ];

__device__ __nv_bfloat16 g_qh[SEQ * DM],  g_ql[SEQ * DM];
__device__ __nv_bfloat16 g_kh[SEQ * DM],  g_kl[SEQ * DM];
__device__ __nv_bfloat16 g_vh[SEQ * DM],  g_vl[SEQ * DM];
__device__ __nv_bfloat16 g_ch[SEQ * DM],  g_cl[SEQ * DM];
__device__ __nv_bfloat16 g_Wqh[DM * DM], g_Wql[DM * DM];
__device__ __nv_bfloat16 g_Wkh[DM * DM], g_Wkl[DM * DM];
__device__ __nv_bfloat16 g_Wvh[DM * DM], g_Wvl[DM * DM];
__device__ __nv_bfloat16 g_Woh[DM * DM], g_Wol[DM * DM];

// E = exp(S - m_tile) as single fp16
__device__ __half g_E[(size_t)NH * SEQ * SEQ];

__device__ float g_pmax[NH * 16 * SEQ];
__device__ float g_psum[NH * 16 * SEQ];

// ===========================================================================
// Split-precision prep: x -> (bf16 hi, bf16 lo)
// ===========================================================================
struct PrepBatch {
    const float* src[8];
    __nv_bfloat16* hi[8];
    __nv_bfloat16* lo[8];
    int n4[8];
};

__global__ __launch_bounds__(256) void split_prep(PrepBatch pb)
{
    int z = blockIdx.z;
    int i = blockIdx.x * 256 + threadIdx.x;
    if (i >= pb.n4[z]) return;
    float4 v = ((const float4*)pb.src[z])[i];
    __nv_bfloat16 h0, h1, h2, h3, l0, l1, l2, l3;
    split2(v.x, h0, l0); split2(v.y, h1, l1);
    split2(v.z, h2, l2); split2(v.w, h3, l3);
    __nv_bfloat162* hp = (__nv_bfloat162*)pb.hi[z];
    __nv_bfloat162* lp = (__nv_bfloat162*)pb.lo[z];
    hp[2 * i]     = __nv_bfloat162(h0, h1);
    hp[2 * i + 1] = __nv_bfloat162(h2, h3);
    lp[2 * i]     = __nv_bfloat162(l0, l1);
    lp[2 * i + 1] = __nv_bfloat162(l2, l3);
}

// ===========================================================================
// mma.sync split-bf16 GEMM: C = A @ W^T + bias. (validated)
// Output: fp32 (C) | bf16 split (Ch/Cl) | fp16 split (Hh/Hl)
// ===========================================================================
#define GP 40
#define TILE_B (128 * GP * 2)
#define STAGE_B (4 * TILE_B)
#define GEMM_SMEM (2 * STAGE_B)

struct GemmPtrs {
    const __nv_bfloat16 *Ah, *Al, *Bh, *Bl;
    const float* bias;
    float* C;
    __nv_bfloat16 *Ch, *Cl;
    __half *Hh, *Hl;
};
struct GemmBatch { GemmPtrs g[3]; };

__global__ __launch_bounds__(256, 2) void gemm_mma(GemmBatch batch)
{
    GemmPtrs gp = batch.g[blockIdx.z];
    extern __shared__ char smem[];
    uint32_t sb = smem_to_u32(smem);

    const int tid  = threadIdx.x;
    const int lane = tid & 31;
    const int wid  = tid >> 5;
    const int wm   = wid >> 1;
    const int wn   = wid & 1;
    const int bm   = blockIdx.y * 128;
    const int bn   = blockIdx.x * 128;

    const __nv_bfloat16* tp[4] = { gp.Ah, gp.Al, gp.Bh, gp.Bl };

    float acc[2][8][4];
#pragma unroll
    for (int i = 0; i < 2; ++i)
#pragma unroll
        for (int j = 0; j < 8; ++j)
#pragma unroll
            for (int c = 0; c < 4; ++c) acc[i][j][c] = 0.f;

    auto issue_stage = [&](int it, int s) {
#pragma unroll
        for (int j = 0; j < 8; ++j) {
            int c2  = tid + j * 256;
            int tt  = c2 >> 9;
            int idx = c2 & 511;
            int r   = idx >> 2;
            int c   = idx & 3;
            uint32_t sm = sb + (uint32_t)(s * STAGE_B + tt * TILE_B + r * 80 + c * 16);
            int grow = ((tt < 2) ? bm : bn) + r;
            const __nv_bfloat16* g8 = tp[tt] + (size_t)grow * DM + it * 32 + c * 8;
            CP_ASYNC16(sm, g8);
        }
        CP_COMMIT();
    };

    issue_stage(0, 0);

    for (int it = 0; it < DM / 32; ++it) {
        const int s = it & 1;
        if (it + 1 < DM / 32) { issue_stage(it + 1, (it + 1) & 1); CP_WAIT1(); }
        else                  { CP_WAIT0(); }
        __syncthreads();

        const uint32_t base = sb + s * STAGE_B;
        const uint32_t aH = base;
        const uint32_t aL = base + TILE_B;
        const uint32_t bH = base + 2 * TILE_B;
        const uint32_t bL = base + 3 * TILE_B;
        const int brow = (lane & 7) + ((lane >> 4) << 3);

#pragma unroll
        for (int ks = 0; ks < 2; ++ks) {
            const uint32_t aoff = (uint32_t)((wm * 32 + (lane & 15)) * 80 + ks * 32 + (lane >> 4) * 16);
            uint32_t ah0[4], ah1[4], al0[4], al1[4];
            LDSM_X4(ah0[0], ah0[1], ah0[2], ah0[3], aH + aoff);
            LDSM_X4(ah1[0], ah1[1], ah1[2], ah1[3], aH + aoff + 16 * 80);
            LDSM_X4(al0[0], al0[1], al0[2], al0[3], aL + aoff);
            LDSM_X4(al1[0], al1[1], al1[2], al1[3], aL + aoff + 16 * 80);

            const uint32_t bko = (uint32_t)(ks * 32 + ((lane >> 3) & 1) * 16);
            uint32_t bh[4][4], bl[4][4];
#pragma unroll
            for (int p = 0; p < 4; ++p) {
                uint32_t boff = (uint32_t)((wn * 64 + p * 16 + brow) * 80) + bko;
                LDSM_X4(bh[p][0], bh[p][1], bh[p][2], bh[p][3], bH + boff);
                LDSM_X4(bl[p][0], bl[p][1], bl[p][2], bl[p][3], bL + boff);
            }

#pragma unroll
            for (int mf = 0; mf < 2; ++mf) {
                const uint32_t* Ah_ = mf ? ah1 : ah0;
                const uint32_t* Al_ = mf ? al1 : al0;
#pragma unroll
                for (int p = 0; p < 4; ++p) {
                    MMA16816(acc[mf][2 * p],     Ah_, bh[p][0], bh[p][1]);
                    MMA16816(acc[mf][2 * p + 1], Ah_, bh[p][2], bh[p][3]);
                    MMA16816(acc[mf][2 * p],     Ah_, bl[p][0], bl[p][1]);
                    MMA16816(acc[mf][2 * p + 1], Ah_, bl[p][2], bl[p][3]);
                    MMA16816(acc[mf][2 * p],     Al_, bh[p][0], bh[p][1]);
                    MMA16816(acc[mf][2 * p + 1], Al_, bh[p][2], bh[p][3]);
                }
            }
        }
        __syncthreads();
    }

    const int l4 = lane >> 2;
    const int l2 = (lane & 3) * 2;
#pragma unroll
    for (int mf = 0; mf < 2; ++mf) {
        int r0 = bm + wm * 32 + mf * 16 + l4;
#pragma unroll
        for (int nf = 0; nf < 8; ++nf) {
            int col = bn + wn * 64 + nf * 8 + l2;
            float2 bb = *(const float2*)&gp.bias[col];
            float v00 = acc[mf][nf][0] + bb.x, v01 = acc[mf][nf][1] + bb.y;
            float v10 = acc[mf][nf][2] + bb.x, v11 = acc[mf][nf][3] + bb.y;
            if (gp.Ch) {
                __nv_bfloat16 h0, h1, l0h, l1h;
                split2(v00, h0, l0h); split2(v01, h1, l1h);
                *(__nv_bfloat162*)&gp.Ch[(size_t)r0 * DM + col] = __nv_bfloat162(h0, h1);
                *(__nv_bfloat162*)&gp.Cl[(size_t)r0 * DM + col] = __nv_bfloat162(l0h, l1h);
                split2(v10, h0, l0h); split2(v11, h1, l1h);
                *(__nv_bfloat162*)&gp.Ch[(size_t)(r0 + 8) * DM + col] = __nv_bfloat162(h0, h1);
                *(__nv_bfloat162*)&gp.Cl[(size_t)(r0 + 8) * DM + col] = __nv_bfloat162(l0h, l1h);
            } else if (gp.Hh) {
                __half h0, h1, l0h, l1h;
                split2h(v00, h0, l0h); split2h(v01, h1, l1h);
                *(__half2*)&gp.Hh[(size_t)r0 * DM + col] = __halves2half2(h0, h1);
                *(__half2*)&gp.Hl[(size_t)r0 * DM + col] = __halves2half2(l0h, l1h);
                split2h(v10, h0, l0h); split2h(v11, h1, l1h);
                *(__half2*)&gp.Hh[(size_t)(r0 + 8) * DM + col] = __halves2half2(h0, h1);
                *(__half2*)&gp.Hl[(size_t)(r0 + 8) * DM + col] = __halves2half2(l0h, l1h);
            } else {
                *(float2*)&gp.C[(size_t)r0 * DM + col]       = make_float2(v00, v01);
                *(float2*)&gp.C[(size_t)(r0 + 8) * DM + col] = make_float2(v10, v11);
            }
        }
    }
}

// ===========================================================================
// attn_scores: block = (q-tile, head); loops over 16 k-tiles with
// double-buffered K. Q hi/lo resident in smem. Per k-tile: 3-term scores,
// mask+scale, tile softmax stats, store E = exp(S - m_kt) fp16.
// smem: QH|QL (36864) + K stages (2x36864) + max/sum (2048) = 112640 B
// ===========================================================================
#define SC_PITCH 144
#define SC_TILE (128 * SC_PITCH)            // 18432
#define SC_OFF_K (2 * SC_TILE)              // 36864
#define SC_KSTAGE (2 * SC_TILE)             // 36864
#define SC_OFF_MAX (SC_OFF_K + 2 * SC_KSTAGE)   // 110592
#define SC_OFF_SUM (SC_OFF_MAX + 1024)          // 111616
#define SC_SMEM    (SC_OFF_SUM + 1024)          // 112640

__global__ __launch_bounds__(256, 2) void attn_scores(
    const __nv_bfloat16* __restrict__ Qh, const __nv_bfloat16* __restrict__ Ql,
    const __nv_bfloat16* __restrict__ Kh, const __nv_bfloat16* __restrict__ Kl,
    const int* __restrict__ mask,
    __half* __restrict__ E,
    float* __restrict__ pmax, float* __restrict__ psum)
{
    extern __shared__ char smem[];
    uint32_t sb = smem_to_u32(smem);
    const int tid = threadIdx.x;
    const int lane = tid & 31;
    const int wid = tid >> 5;
    const int wm = wid >> 1;
    const int wn = wid & 1;
    const int h  = blockIdx.y;
    const int qb = blockIdx.x * 128;

    // Q tiles (hi, lo) loaded once
    {
#pragma unroll
        for (int j = 0; j < 8; ++j) {
            int c2  = tid + j * 256;        // 0..2047
            int mat = c2 >> 10;
            int idx = c2 & 1023;
            int r = idx >> 3, c = idx & 7;
            uint32_t sm = sb + (uint32_t)(mat * SC_TILE + r * SC_PITCH + c * 16);
            CP_ASYNC16(sm, (mat ? Ql : Qh) + (size_t)(qb + r) * DM + h * DKH + c * 8);
        }
    }
    auto issue_k = [&](int kt, int s) {
#pragma unroll
        for (int j = 0; j < 8; ++j) {
            int c2  = tid + j * 256;
            int mat = c2 >> 10;
            int idx = c2 & 1023;
            int r = idx >> 3, c = idx & 7;
            uint32_t sm = sb + (uint32_t)(SC_OFF_K + s * SC_KSTAGE + mat * SC_TILE + r * SC_PITCH + c * 16);
            CP_ASYNC16(sm, (mat ? Kl : Kh) + (size_t)(kt * 128 + r) * DM + h * DKH + c * 8);
        }
    };
    issue_k(0, 0);
    CP_COMMIT();    // group: Q + K0

    float* sMax = (float*)(smem + SC_OFF_MAX);
    float* sSum = (float*)(smem + SC_OFF_SUM);
    const uint32_t aH = sb, aL = sb + SC_TILE;
    const int brow = (lane & 7) + ((lane >> 4) << 3);
    const int c0 = (lane & 3) * 2;
    const int r0l = lane >> 2;

    for (int kt = 0; kt < 16; ++kt) {
        const int s = kt & 1;
        if (kt + 1 < 16) { issue_k(kt + 1, s ^ 1); CP_COMMIT(); CP_WAIT1(); }
        else             { CP_WAIT0(); }
        __syncthreads();

        const uint32_t bH = sb + SC_OFF_K + s * SC_KSTAGE;
        const uint32_t bL = bH + SC_TILE;

        float acc[2][8][4];
#pragma unroll
        for (int i = 0; i < 2; ++i)
#pragma unroll
            for (int j = 0; j < 8; ++j)
#pragma unroll
                for (int c = 0; c < 4; ++c) acc[i][j][c] = 0.f;

#pragma unroll
        for (int ks = 0; ks < 4; ++ks) {
            uint32_t aoff = (uint32_t)((wm * 32 + (lane & 15)) * SC_PITCH + ks * 32 + (lane >> 4) * 16);
            uint32_t ah0[4], ah1[4], al0[4], al1[4];
            LDSM_X4(ah0[0], ah0[1], ah0[2], ah0[3], aH + aoff);
            LDSM_X4(ah1[0], ah1[1], ah1[2], ah1[3], aH + aoff + 16 * SC_PITCH);
            LDSM_X4(al0[0], al0[1], al0[2], al0[3], aL + aoff);
            LDSM_X4(al1[0], al1[1], al1[2], al1[3], aL + aoff + 16 * SC_PITCH);
            uint32_t bko = (uint32_t)(ks * 32 + ((lane >> 3) & 1) * 16);
#pragma unroll
            for (int p = 0; p < 4; ++p) {
                uint32_t boff = (uint32_t)((wn * 64 + p * 16 + brow) * SC_PITCH) + bko;
                uint32_t bh0, bh1, bh2, bh3, bl0, bl1, bl2, bl3;
                LDSM_X4(bh0, bh1, bh2, bh3, bH + boff);
                LDSM_X4(bl0, bl1, bl2, bl3, bL + boff);
                MMA16816(acc[0][2 * p],     ah0, bh0, bh1);
                MMA16816(acc[0][2 * p + 1], ah0, bh2, bh3);
                MMA16816(acc[1][2 * p],     ah1, bh0, bh1);
                MMA16816(acc[1][2 * p + 1], ah1, bh2, bh3);
                MMA16816(acc[0][2 * p],     ah0, bl0, bl1);
                MMA16816(acc[0][2 * p + 1], ah0, bl2, bl3);
                MMA16816(acc[1][2 * p],     ah1, bl0, bl1);
                MMA16816(acc[1][2 * p + 1], ah1, bl2, bl3);
                MMA16816(acc[0][2 * p],     al0, bh0, bh1);
                MMA16816(acc[0][2 * p + 1], al0, bh2, bh3);
                MMA16816(acc[1][2 * p],     al1, bh0, bh1);
                MMA16816(acc[1][2 * p + 1], al1, bh2, bh3);
            }
        }

        // ---- epilogue: scale+mask, tile max, exp, stats, store E ----
        const int kb = kt * 128;
#pragma unroll
        for (int mf = 0; mf < 2; ++mf)
#pragma unroll
            for (int nf = 0; nf < 8; ++nf) {
                int col = wn * 64 + nf * 8 + c0;
                bool k0 = mask[kb + col] != 0, k1 = mask[kb + col + 1] != 0;
                acc[mf][nf][0] = k0 ? acc[mf][nf][0] * 0.125f : -1e9f;
                acc[mf][nf][1] = k1 ? acc[mf][nf][1] * 0.125f : -1e9f;
                acc[mf][nf][2] = k0 ? acc[mf][nf][2] * 0.125f : -1e9f;
                acc[mf][nf][3] = k1 ? acc[mf][nf][3] * 0.125f : -1e9f;
            }

        float rmax[2][2];
#pragma unroll
        for (int mf = 0; mf < 2; ++mf)
#pragma unroll
            for (int hf = 0; hf < 2; ++hf) {
                float m = -INFINITY;
#pragma unroll
                for (int nf = 0; nf < 8; ++nf) {
                    m = fmaxf(m, acc[mf][nf][hf * 2]);
                    m = fmaxf(m, acc[mf][nf][hf * 2 + 1]);
                }
                m = fmaxf(m, __shfl_xor_sync(0xffffffffu, m, 1));
                m = fmaxf(m, __shfl_xor_sync(0xffffffffu, m, 2));
                if ((lane & 3) == 0) sMax[(wm * 32 + mf * 16 + hf * 8 + r0l) * 2 + wn] = m;
            }
        __syncthreads();
#pragma unroll
        for (int mf = 0; mf < 2; ++mf)
#pragma unroll
            for (int hf = 0; hf < 2; ++hf) {
                int row = wm * 32 + mf * 16 + hf * 8 + r0l;
                float M = fmaxf(sMax[row * 2], sMax[row * 2 + 1]);
                rmax[mf][hf] = M;
                float s2 = 0.f;
#pragma unroll
                for (int nf = 0; nf < 8; ++nf) {
                    float e0 = __expf(acc[mf][nf][hf * 2]     - M);
                    float e1 = __expf(acc[mf][nf][hf * 2 + 1] - M);
                    acc[mf][nf][hf * 2]     = e0;
                    acc[mf][nf][hf * 2 + 1] = e1;
                    s2 += e0 + e1;
                }
                s2 += __shfl_xor_sync(0xffffffffu, s2, 1);
                s2 += __shfl_xor_sync(0xffffffffu, s2, 2);
                if ((lane & 3) == 0) sSum[row * 2 + wn] = s2;
            }
        __syncthreads();
        if (wn == 0 && (lane & 3) == 0) {
#pragma unroll
            for (int mf = 0; mf < 2; ++mf)
#pragma unroll
                for (int hf = 0; hf < 2; ++hf) {
                    int row = wm * 32 + mf * 16 + hf * 8 + r0l;
                    size_t sidx = (size_t)(h * 16 + kt) * SEQ + qb + row;
                    pmax[sidx] = rmax[mf][hf];
                    psum[sidx] = sSum[row * 2] + sSum[row * 2 + 1];
                }
        }

#pragma unroll
        for (int mf = 0; mf < 2; ++mf)
#pragma unroll
            for (int hf = 0; hf < 2; ++hf) {
                int qrow = qb + wm * 32 + mf * 16 + hf * 8 + r0l;
                size_t rbase = ((size_t)h * SEQ + qrow) * SEQ + kb;
#pragma unroll
                for (int nf = 0; nf < 8; ++nf) {
                    int col = wn * 64 + nf * 8 + c0;
                    *(__half2*)&E[rbase + col] =
                        __floats2half2_rn(acc[mf][nf][hf * 2], acc[mf][nf][hf * 2 + 1]);
                }
            }
    }
}

// ===========================================================================
// attn_pv2: K-chunk 64. mma on RAW E into per-iter partial, fold acc += c*p;
// attn emitted straight from E smem. Split bf16 ctx out.
// ===========================================================================
#define PA_TILE (128 * 144)                      // 18432 (E tile, 64 cols fp16)
#define PB_TILE (64 * 144)                       // 9216 per V matrix
#define PV_STAGE (PA_TILE + 2 * PB_TILE)         // 36864
#define PV_OFF_ST (2 * PV_STAGE)                 // 73728
#define PV_SMEM (PV_OFF_ST + 16 * 128 * 4)       // 81920

__global__ __launch_bounds__(256, 2) void attn_pv2(
    const __half* __restrict__ E,
    const __half* __restrict__ Vh, const __half* __restrict__ Vl,
    const float* __restrict__ pmax, const float* __restrict__ psum,
    float* __restrict__ attn,
    __nv_bfloat16* __restrict__ Ch, __nv_bfloat16* __restrict__ Cl)
{
    extern __shared__ char smem[];
    uint32_t sb = smem_to_u32(smem);

    const int tid  = threadIdx.x;
    const int lane = tid & 31;
    const int wid  = tid >> 5;
    const int wm   = wid >> 1;       // 0..3 (32 q-rows)
    const int wn   = wid & 1;        // 0..1 (32 dims)
    const int h    = blockIdx.y;
    const int bm   = blockIdx.x * 128;

    float acc[2][4][4];
#pragma unroll
    for (int i = 0; i < 2; ++i)
#pragma unroll
        for (int j = 0; j < 4; ++j)
#pragma unroll
            for (int c = 0; c < 4; ++c) acc[i][j][c] = 0.f;

    auto issue_stage = [&](int it, int s) {
#pragma unroll
        for (int j = 0; j < 8; ++j) {
            int c2 = tid + j * 256;            // 0..2047
            uint32_t sm;
            const __half* g8;
            if (c2 < 1024) {
                int r = c2 >> 3, c = c2 & 7;   // E: 128 rows x 8 chunks (128B)
                sm = sb + (uint32_t)(s * PV_STAGE + r * 144 + c * 16);
                g8 = E + ((size_t)h * SEQ + bm + r) * SEQ + it * 64 + c * 8;
            } else {
                int c2b = c2 - 1024;
                int mat = c2b >> 9;            // 0=Vh 1=Vl
                int idx = c2b & 511;
                int r = idx >> 3, c = idx & 7; // V: 64 rows x 8 chunks
                sm = sb + (uint32_t)(s * PV_STAGE + PA_TILE + mat * PB_TILE + r * 144 + c * 16);
                g8 = (mat ? Vl : Vh) + (size_t)(it * 64 + r) * DM + h * DKH + c * 8;
            }
            CP_ASYNC16(sm, g8);
        }
        CP_COMMIT();
    };

    issue_stage(0, 0);

    // c table: c[kt][row] = exp(m_kt - M) / Z
    float* sC = (float*)(smem + PV_OFF_ST);
    if (tid < 128) {
        int qrow = bm + tid;
        float pm[16];
        float M = -INFINITY;
#pragma unroll
        for (int kt = 0; kt < 16; ++kt) {
            pm[kt] = pmax[(size_t)(h * 16 + kt) * SEQ + qrow];
            M = fmaxf(M, pm[kt]);
        }
        float S = 0.f;
#pragma unroll
        for (int kt = 0; kt < 16; ++kt)
            S += psum[(size_t)(h * 16 + kt) * SEQ + qrow] * __expf(pm[kt] - M);
        float inv = 1.0f / S;
#pragma unroll
        for (int kt = 0; kt < 16; ++kt)
            sC[kt * 128 + tid] = __expf(pm[kt] - M) * inv;
    }

    const int l4 = lane >> 2;

    for (int it = 0; it < SEQ / 64; ++it) {
        const int s = it & 1;
        if (it + 1 < SEQ / 64) { issue_stage(it + 1, s ^ 1); CP_WAIT1(); }
        else                   { CP_WAIT0(); }
        __syncthreads();

        const uint32_t aEb = sb + s * PV_STAGE;
        const uint32_t vHb = aEb + PA_TILE;
        const uint32_t vLb = vHb + PB_TILE;
        const float* cRow = &sC[(it >> 1) * 128];

        // ---- mma on raw E into per-iteration partial ----
        float accP[2][4][4];
#pragma unroll
        for (int i = 0; i < 2; ++i)
#pragma unroll
            for (int j = 0; j < 4; ++j)
#pragma unroll
                for (int c = 0; c < 4; ++c) accP[i][j][c] = 0.f;

#pragma unroll
        for (int ks = 0; ks < 4; ++ks) {
            uint32_t aoff = (uint32_t)((wm * 32 + (lane & 15)) * 144 + ks * 32 + (lane >> 4) * 16);
            uint32_t e0[4], e1[4];
            LDSM_X4(e0[0], e0[1], e0[2], e0[3], aEb + aoff);
            LDSM_X4(e1[0], e1[1], e1[2], e1[3], aEb + aoff + 16 * 144);

            const int vrow = ks * 16 + ((lane >> 3) & 1) * 8 + (lane & 7);
            uint32_t bh[2][4], bl[2][4];
#pragma unroll
            for (int p = 0; p < 2; ++p) {
                int vcol = wn * 32 + p * 16 + ((lane >> 4) & 1) * 8;
                uint32_t voff = (uint32_t)(vrow * 144 + vcol * 2);
                LDSM_X4T(bh[p][0], bh[p][1], bh[p][2], bh[p][3], vHb + voff);
                LDSM_X4T(bl[p][0], bl[p][1], bl[p][2], bl[p][3], vLb + voff);
            }
#pragma unroll
            for (int mf = 0; mf < 2; ++mf) {
                const uint32_t* A_ = mf ? e1 : e0;
#pragma unroll
                for (int p = 0; p < 2; ++p) {
                    MMA16816H(accP[mf][2 * p],     A_, bh[p][0], bh[p][1]);
                    MMA16816H(accP[mf][2 * p + 1], A_, bh[p][2], bh[p][3]);
                    MMA16816H(accP[mf][2 * p],     A_, bl[p][0], bl[p][1]);
                    MMA16816H(accP[mf][2 * p + 1], A_, bl[p][2], bl[p][3]);
                }
            }
        }

        // fold: acc += c[row] * partial
#pragma unroll
        for (int mf = 0; mf < 2; ++mf) {
            float cv0 = cRow[wm * 32 + mf * 16 + l4];
            float cv1 = cRow[wm * 32 + mf * 16 + 8 + l4];
#pragma unroll
            for (int nf = 0; nf < 4; ++nf) {
                acc[mf][nf][0] += cv0 * accP[mf][nf][0];
                acc[mf][nf][1] += cv0 * accP[mf][nf][1];
                acc[mf][nf][2] += cv1 * accP[mf][nf][2];
                acc[mf][nf][3] += cv1 * accP[mf][nf][3];
            }
        }

        // ---- emit attn = E * c directly from smem (read-only) ----
        {
            const char* pa = smem + s * PV_STAGE;
#pragma unroll
            for (int j = 0; j < 4; ++j) {
                int idx = tid + j * 256;       // 0..1023
                int r = idx >> 3, c = idx & 7;
                uint4 ue = *(const uint4*)(pa + r * 144 + c * 16);
                const __half2* eb = (const __half2*)&ue;
                float cv = cRow[r];
                float p[8];
#pragma unroll
                for (int e = 0; e < 4; ++e) {
                    p[2 * e]     = __low2float(eb[e])  * cv;
                    p[2 * e + 1] = __high2float(eb[e]) * cv;
                }
                float* ga = attn + ((size_t)h * SEQ + bm + r) * SEQ + it * 64 + c * 8;
                *(float4*)ga       = make_float4(p[0], p[1], p[2], p[3]);
                *(float4*)(ga + 4) = make_float4(p[4], p[5], p[6], p[7]);
            }
        }
        __syncthreads();
    }

    const int l2 = (lane & 3) * 2;
#pragma unroll
    for (int mf = 0; mf < 2; ++mf) {
        int q = bm + wm * 32 + mf * 16 + l4;
#pragma unroll
        for (int nf = 0; nf < 4; ++nf) {
            int col = h * DKH + wn * 32 + nf * 8 + l2;
            __nv_bfloat16 h0, h1, l0, l1;
            split2(acc[mf][nf][0], h0, l0);
            split2(acc[mf][nf][1], h1, l1);
            *(__nv_bfloat162*)&Ch[(size_t)q * DM + col] = __nv_bfloat162(h0, h1);
            *(__nv_bfloat162*)&Cl[(size_t)q * DM + col] = __nv_bfloat162(l0, l1);
            split2(acc[mf][nf][2], h0, l0);
            split2(acc[mf][nf][3], h1, l1);
            *(__nv_bfloat162*)&Ch[(size_t)(q + 8) * DM + col] = __nv_bfloat162(h0, h1);
            *(__nv_bfloat162*)&Cl[(size_t)(q + 8) * DM + col] = __nv_bfloat162(l0, l1);
        }
    }
}

// ===========================================================================
extern "C" void kernel_launch(void* const* d_in, const int* in_sizes, int n_in,
                              void* d_out, int out_size)
{
    const float* q    = (const float*)d_in[0];
    const float* k    = (const float*)d_in[1];
    const float* v    = (const float*)d_in[2];
    const int*   mask = (const int*)  d_in[3];
    const float* Wq   = (const float*)d_in[4];
    const float* bq   = (const float*)d_in[5];
    const float* Wk   = (const float*)d_in[6];
    const float* bk   = (const float*)d_in[7];
    const float* Wv   = (const float*)d_in[8];
    const float* bv   = (const float*)d_in[9];
    const float* Wo   = (const float*)d_in[10];
    const float* bo   = (const float*)d_in[11];

    float *Qp, *Kp, *Vp, *Ap, *Op, *pmaxp, *psump;
    cudaGetSymbolAddress((void**)&Qp, g_Q);
    cudaGetSymbolAddress((void**)&Kp, g_K);
    cudaGetSymbolAddress((void**)&Vp, g_V);
    cudaGetSymbolAddress((void**)&Ap, g_ATTN);
    cudaGetSymbolAddress((void**)&Op, g_OUT);
    cudaGetSymbolAddress((void**)&pmaxp, g_pmax);
    cudaGetSymbolAddress((void**)&psump, g_psum);

    __nv_bfloat16 *qh, *ql, *kh, *kl, *vh, *vl, *ch, *cl;
    __nv_bfloat16 *Wqh, *Wql, *Wkh, *Wkl, *Wvh, *Wvl, *Woh, *Wol;
    __half* Ep;
    cudaGetSymbolAddress((void**)&qh, g_qh);   cudaGetSymbolAddress((void**)&ql, g_ql);
    cudaGetSymbolAddress((void**)&kh, g_kh);   cudaGetSymbolAddress((void**)&kl, g_kl);
    cudaGetSymbolAddress((void**)&vh, g_vh);   cudaGetSymbolAddress((void**)&vl, g_vl);
    cudaGetSymbolAddress((void**)&ch, g_ch);   cudaGetSymbolAddress((void**)&cl, g_cl);
    cudaGetSymbolAddress((void**)&Ep, g_E);
    cudaGetSymbolAddress((void**)&Wqh, g_Wqh); cudaGetSymbolAddress((void**)&Wql, g_Wql);
    cudaGetSymbolAddress((void**)&Wkh, g_Wkh); cudaGetSymbolAddress((void**)&Wkl, g_Wkl);
    cudaGetSymbolAddress((void**)&Wvh, g_Wvh); cudaGetSymbolAddress((void**)&Wvl, g_Wvl);
    cudaGetSymbolAddress((void**)&Woh, g_Woh); cudaGetSymbolAddress((void**)&Wol, g_Wol);

    __nv_bfloat16* pqh = (__nv_bfloat16*)Qp; __nv_bfloat16* pql = pqh + (size_t)SEQ * DM;
    __nv_bfloat16* pkh = (__nv_bfloat16*)Kp; __nv_bfloat16* pkl = pkh + (size_t)SEQ * DM;
    __half* pvh = (__half*)Vp; __half* pvl = pvh + (size_t)SEQ * DM;

    const size_t OUT_ELEMS  = (size_t)SEQ * DM;
    const size_t ATTN_ELEMS = (size_t)NH * SEQ * SEQ;

    float* outp = (float*)d_out;
    float* attnp;
    if ((size_t)out_size >= OUT_ELEMS + ATTN_ELEMS) {
        attnp = outp + OUT_ELEMS;
    } else if ((size_t)out_size == ATTN_ELEMS) {
        attnp = (float*)d_out;
        outp  = Op;
    } else {
        attnp = Ap;
    }

    cudaFuncSetAttribute(gemm_mma,
                         cudaFuncAttributeMaxDynamicSharedMemorySize, GEMM_SMEM);
    cudaFuncSetAttribute(attn_scores,
                         cudaFuncAttributeMaxDynamicSharedMemorySize, SC_SMEM);
    cudaFuncSetAttribute(attn_pv2,
                         cudaFuncAttributeMaxDynamicSharedMemorySize, PV_SMEM);

    // 1) split inputs + weights
    {
        PrepBatch pb;
        pb.src[0] = q;  pb.hi[0] = qh;  pb.lo[0] = ql;  pb.n4[0] = SEQ * DM / 4;
        pb.src[1] = k;  pb.hi[1] = kh;  pb.lo[1] = kl;  pb.n4[1] = SEQ * DM / 4;
        pb.src[2] = v;  pb.hi[2] = vh;  pb.lo[2] = vl;  pb.n4[2] = SEQ * DM / 4;
        pb.src[3] = Wq; pb.hi[3] = Wqh; pb.lo[3] = Wql; pb.n4[3] = DM * DM / 4;
        pb.src[4] = Wk; pb.hi[4] = Wkh; pb.lo[4] = Wkl; pb.n4[4] = DM * DM / 4;
        pb.src[5] = Wv; pb.hi[5] = Wvh; pb.lo[5] = Wvl; pb.n4[5] = DM * DM / 4;
        pb.src[6] = Wo; pb.hi[6] = Woh; pb.lo[6] = Wol; pb.n4[6] = DM * DM / 4;
        pb.src[7] = q;  pb.hi[7] = qh;  pb.lo[7] = ql;  pb.n4[7] = 0;
        dim3 pg((SEQ * DM / 4 + 255) / 256, 1, 7);
        split_prep<<<pg, 256>>>(pb);
    }

    // 2) Q/K/V projections -> Q,K bf16 split; V fp16 split
    {
        GemmBatch gb;
        gb.g[0] = { qh, ql, Wqh, Wql, bq, nullptr, pqh, pql, nullptr, nullptr };
        gb.g[1] = { kh, kl, Wkh, Wkl, bk, nullptr, pkh, pkl, nullptr, nullptr };
        gb.g[2] = { vh, vl, Wvh, Wvl, bv, nullptr, nullptr, nullptr, pvh, pvl };
        gemm_mma<<<dim3(DM / 128, SEQ / 128, 3), 256, GEMM_SMEM>>>(gb);
    }

    // 3) scores: per (q-tile, head) block streams all K tiles
    attn_scores<<<dim3(SEQ / 128, NH), 256, SC_SMEM>>>(
        pqh, pql, pkh, pkl, mask, Ep, pmaxp, psump);

    // 4) fused rescale + attn-emit + P@V (fp16 mma, deferred scaling) -> split ctx
    attn_pv2<<<dim3(SEQ / 128, NH), 256, PV_SMEM>>>(
        Ep, pvh, pvl, pmaxp, psump, attnp, ch, cl);

    // 5) output projection (fp32 out)
    {
        GemmBatch gb;
        gb.g[0] = { ch, cl, Woh, Wol, bo, outp, nullptr, nullptr, nullptr, nullptr };
        gb.g[1] = gb.g[0];
        gb.g[2] = gb.g[0];
        gemm_mma<<<dim3(DM / 128, SEQ / 128, 1), 256, GEMM_SMEM>>>(gb);
    }
}

// round 14
// speedup vs baseline: 1.0652x; 1.0652x over previous
#include <cuda_runtime.h>
#include <cuda_bf16.h>
#include <cuda_fp16.h>
#include <math.h>
#include <stdint.h>

// Problem constants
#define SEQ 2048
#define DM  1024
#define NH  16
#define DKH 64

// ===========================================================================
// Portable PTX helpers (base compute_103 target)
// ===========================================================================
__device__ __forceinline__ uint32_t smem_to_u32(const void* smem_ptr) {
    uint32_t addr;
    asm("{ .reg .u64 tmp; cvta.to.shared.u64 tmp, %1; cvt.u32.u64 %0, tmp; }"
        : "=r"(addr) : "l"(smem_ptr));
    return addr;
}

#define LDSM_X4(r0, r1, r2, r3, addr) \
    asm volatile("ldmatrix.sync.aligned.m8n8.x4.shared.b16 {%0,%1,%2,%3}, [%4];" \
        : "=r"(r0), "=r"(r1), "=r"(r2), "=r"(r3) : "r"(addr))

#define LDSM_X4T(r0, r1, r2, r3, addr) \
    asm volatile("ldmatrix.sync.aligned.m8n8.x4.trans.shared.b16 {%0,%1,%2,%3}, [%4];" \
        : "=r"(r0), "=r"(r1), "=r"(r2), "=r"(r3) : "r"(addr))

#define MMA16816(c, a, b0, b1) \
    asm volatile("mma.sync.aligned.m16n8k16.row.col.f32.bf16.bf16.f32 " \
        "{%0,%1,%2,%3},{%4,%5,%6,%7},{%8,%9},{%0,%1,%2,%3};" \
        : "+f"((c)[0]), "+f"((c)[1]), "+f"((c)[2]), "+f"((c)[3]) \
        : "r"((a)[0]), "r"((a)[1]), "r"((a)[2]), "r"((a)[3]), "r"(b0), "r"(b1))

#define MMA16816H(c, a, b0, b1) \
    asm volatile("mma.sync.aligned.m16n8k16.row.col.f32.f16.f16.f32 " \
        "{%0,%1,%2,%3},{%4,%5,%6,%7},{%8,%9},{%0,%1,%2,%3};" \
        : "+f"((c)[0]), "+f"((c)[1]), "+f"((c)[2]), "+f"((c)[3]) \
        : "r"((a)[0]), "r"((a)[1]), "r"((a)[2]), "r"((a)[3]), "r"(b0), "r"(b1))

#define CP_ASYNC16(smaddr, gptr) \
    asm volatile("cp.async.cg.shared.global [%0], [%1], 16;" \
        :: "r"(smaddr), "l"(gptr))
#define CP_COMMIT() asm volatile("cp.async.commit_group;" ::: "memory")
#define CP_WAIT0()  asm volatile("cp.async.wait_group 0;" ::: "memory")
#define CP_WAIT1()  asm volatile("cp.async.wait_group 1;" ::: "memory")

__device__ __forceinline__ void split2(float x, __nv_bfloat16& h, __nv_bfloat16& l) {
    h = __float2bfloat16(x);
    l = __float2bfloat16(x - __bfloat162float(h));
}
__device__ __forceinline__ void split2h(float x, __half& h, __half& l) {
    h = __float2half_rn(x);
    l = __float2half_rn(x - __half2float(h));
}

// ===========================================================================
// Scratch (device globals)
// ===========================================================================
__device__ float g_Q[SEQ * DM];
__device__ float g_K[SEQ * DM];
__device__ float g_V[SEQ * DM];      // reused: fp16 split of projected V (hi|lo)
__device__ float g_OUT[SEQ * DM];
__device__ float g_ATTN[(size_t)NH * SEQ * SEQ];

__device__ __nv_bfloat16 g_qh[SEQ * DM],  g_ql[SEQ * DM];
__device__ __nv_bfloat16 g_kh[SEQ * DM],  g_kl[SEQ * DM];
__device__ __nv_bfloat16 g_vh[SEQ * DM],  g_vl[SEQ * DM];
__device__ __nv_bfloat16 g_ch[SEQ * DM],  g_cl[SEQ * DM];
__device__ __nv_bfloat16 g_Wqh[DM * DM], g_Wql[DM * DM];
__device__ __nv_bfloat16 g_Wkh[DM * DM], g_Wkl[DM * DM];
__device__ __nv_bfloat16 g_Wvh[DM * DM], g_Wvl[DM * DM];
__device__ __nv_bfloat16 g_Woh[DM * DM], g_Wol[DM * DM];

// E = exp(S - m_tile) as single fp16
__device__ __half g_E[(size_t)NH * SEQ * SEQ];

__device__ float g_pmax[NH * 16 * SEQ];
__device__ float g_psum[NH * 16 * SEQ];

// ===========================================================================
// Split-precision prep: x -> (bf16 hi, bf16 lo)
// ===========================================================================
struct PrepBatch {
    const float* src[8];
    __nv_bfloat16* hi[8];
    __nv_bfloat16* lo[8];
    int n4[8];
};

__global__ __launch_bounds__(256) void split_prep(PrepBatch pb)
{
    int z = blockIdx.z;
    int i = blockIdx.x * 256 + threadIdx.x;
    if (i >= pb.n4[z]) return;
    float4 v = ((const float4*)pb.src[z])[i];
    __nv_bfloat16 h0, h1, h2, h3, l0, l1, l2, l3;
    split2(v.x, h0, l0); split2(v.y, h1, l1);
    split2(v.z, h2, l2); split2(v.w, h3, l3);
    __nv_bfloat162* hp = (__nv_bfloat162*)pb.hi[z];
    __nv_bfloat162* lp = (__nv_bfloat162*)pb.lo[z];
    hp[2 * i]     = __nv_bfloat162(h0, h1);
    hp[2 * i + 1] = __nv_bfloat162(h2, h3);
    lp[2 * i]     = __nv_bfloat162(l0, l1);
    lp[2 * i + 1] = __nv_bfloat162(l2, l3);
}

// ===========================================================================
// mma.sync split-bf16 GEMM: C = A @ W^T + bias.
// Output: fp32 (C) | bf16 split (Ch/Cl) | fp16 split (Hh/Hl)
// ===========================================================================
#define GP 40
#define TILE_B (128 * GP * 2)
#define STAGE_B (4 * TILE_B)
#define GEMM_SMEM (2 * STAGE_B)

struct GemmPtrs {
    const __nv_bfloat16 *Ah, *Al, *Bh, *Bl;
    const float* bias;
    float* C;
    __nv_bfloat16 *Ch, *Cl;
    __half *Hh, *Hl;
};
struct GemmBatch { GemmPtrs g[3]; };

__global__ __launch_bounds__(256, 2) void gemm_mma(GemmBatch batch)
{
    GemmPtrs gp = batch.g[blockIdx.z];
    extern __shared__ char smem[];
    uint32_t sb = smem_to_u32(smem);

    const int tid  = threadIdx.x;
    const int lane = tid & 31;
    const int wid  = tid >> 5;
    const int wm   = wid >> 1;
    const int wn   = wid & 1;
    const int bm   = blockIdx.y * 128;
    const int bn   = blockIdx.x * 128;

    const __nv_bfloat16* tp[4] = { gp.Ah, gp.Al, gp.Bh, gp.Bl };

    float acc[2][8][4];
#pragma unroll
    for (int i = 0; i < 2; ++i)
#pragma unroll
        for (int j = 0; j < 8; ++j)
#pragma unroll
            for (int c = 0; c < 4; ++c) acc[i][j][c] = 0.f;

    auto issue_stage = [&](int it, int s) {
#pragma unroll
        for (int j = 0; j < 8; ++j) {
            int c2  = tid + j * 256;
            int tt  = c2 >> 9;
            int idx = c2 & 511;
            int r   = idx >> 2;
            int c   = idx & 3;
            uint32_t sm = sb + (uint32_t)(s * STAGE_B + tt * TILE_B + r * 80 + c * 16);
            int grow = ((tt < 2) ? bm : bn) + r;
            const __nv_bfloat16* g8 = tp[tt] + (size_t)grow * DM + it * 32 + c * 8;
            CP_ASYNC16(sm, g8);
        }
        CP_COMMIT();
    };

    issue_stage(0, 0);

    for (int it = 0; it < DM / 32; ++it) {
        const int s = it & 1;
        if (it + 1 < DM / 32) { issue_stage(it + 1, (it + 1) & 1); CP_WAIT1(); }
        else                  { CP_WAIT0(); }
        __syncthreads();

        const uint32_t base = sb + s * STAGE_B;
        const uint32_t aH = base;
        const uint32_t aL = base + TILE_B;
        const uint32_t bH = base + 2 * TILE_B;
        const uint32_t bL = base + 3 * TILE_B;
        const int brow = (lane & 7) + ((lane >> 4) << 3);

#pragma unroll
        for (int ks = 0; ks < 2; ++ks) {
            const uint32_t aoff = (uint32_t)((wm * 32 + (lane & 15)) * 80 + ks * 32 + (lane >> 4) * 16);
            uint32_t ah0[4], ah1[4], al0[4], al1[4];
            LDSM_X4(ah0[0], ah0[1], ah0[2], ah0[3], aH + aoff);
            LDSM_X4(ah1[0], ah1[1], ah1[2], ah1[3], aH + aoff + 16 * 80);
            LDSM_X4(al0[0], al0[1], al0[2], al0[3], aL + aoff);
            LDSM_X4(al1[0], al1[1], al1[2], al1[3], aL + aoff + 16 * 80);

            const uint32_t bko = (uint32_t)(ks * 32 + ((lane >> 3) & 1) * 16);
            uint32_t bh[4][4], bl[4][4];
#pragma unroll
            for (int p = 0; p < 4; ++p) {
                uint32_t boff = (uint32_t)((wn * 64 + p * 16 + brow) * 80) + bko;
                LDSM_X4(bh[p][0], bh[p][1], bh[p][2], bh[p][3], bH + boff);
                LDSM_X4(bl[p][0], bl[p][1], bl[p][2], bl[p][3], bL + boff);
            }

#pragma unroll
            for (int mf = 0; mf < 2; ++mf) {
                const uint32_t* Ah_ = mf ? ah1 : ah0;
                const uint32_t* Al_ = mf ? al1 : al0;
#pragma unroll
                for (int p = 0; p < 4; ++p) {
                    MMA16816(acc[mf][2 * p],     Ah_, bh[p][0], bh[p][1]);
                    MMA16816(acc[mf][2 * p + 1], Ah_, bh[p][2], bh[p][3]);
                    MMA16816(acc[mf][2 * p],     Ah_, bl[p][0], bl[p][1]);
                    MMA16816(acc[mf][2 * p + 1], Ah_, bl[p][2], bl[p][3]);
                    MMA16816(acc[mf][2 * p],     Al_, bh[p][0], bh[p][1]);
                    MMA16816(acc[mf][2 * p + 1], Al_, bh[p][2], bh[p][3]);
                }
            }
        }
        __syncthreads();
    }

    const int l4 = lane >> 2;
    const int l2 = (lane & 3) * 2;
#pragma unroll
    for (int mf = 0; mf < 2; ++mf) {
        int r0 = bm + wm * 32 + mf * 16 + l4;
#pragma unroll
        for (int nf = 0; nf < 8; ++nf) {
            int col = bn + wn * 64 + nf * 8 + l2;
            float2 bb = *(const float2*)&gp.bias[col];
            float v00 = acc[mf][nf][0] + bb.x, v01 = acc[mf][nf][1] + bb.y;
            float v10 = acc[mf][nf][2] + bb.x, v11 = acc[mf][nf][3] + bb.y;
            if (gp.Ch) {
                __nv_bfloat16 h0, h1, l0h, l1h;
                split2(v00, h0, l0h); split2(v01, h1, l1h);
                *(__nv_bfloat162*)&gp.Ch[(size_t)r0 * DM + col] = __nv_bfloat162(h0, h1);
                *(__nv_bfloat162*)&gp.Cl[(size_t)r0 * DM + col] = __nv_bfloat162(l0h, l1h);
                split2(v10, h0, l0h); split2(v11, h1, l1h);
                *(__nv_bfloat162*)&gp.Ch[(size_t)(r0 + 8) * DM + col] = __nv_bfloat162(h0, h1);
                *(__nv_bfloat162*)&gp.Cl[(size_t)(r0 + 8) * DM + col] = __nv_bfloat162(l0h, l1h);
            } else if (gp.Hh) {
                __half h0, h1, l0h, l1h;
                split2h(v00, h0, l0h); split2h(v01, h1, l1h);
                *(__half2*)&gp.Hh[(size_t)r0 * DM + col] = __halves2half2(h0, h1);
                *(__half2*)&gp.Hl[(size_t)r0 * DM + col] = __halves2half2(l0h, l1h);
                split2h(v10, h0, l0h); split2h(v11, h1, l1h);
                *(__half2*)&gp.Hh[(size_t)(r0 + 8) * DM + col] = __halves2half2(h0, h1);
                *(__half2*)&gp.Hl[(size_t)(r0 + 8) * DM + col] = __halves2half2(l0h, l1h);
            } else {
                *(float2*)&gp.C[(size_t)r0 * DM + col]       = make_float2(v00, v01);
                *(float2*)&gp.C[(size_t)(r0 + 8) * DM + col] = make_float2(v10, v11);
            }
        }
    }
}

// ===========================================================================
// attn_sgemm: E = exp(S - m_tile) fp16 via SMEM-STAGED COALESCED store + stats.
// grid (16 ktiles, 16 qtiles, 16 heads), 256 threads, (256,2).
// E staging pitch 272 B (16-aligned, conflict-free).
// ===========================================================================
#define SG_PITCH 144
#define SG_TILE (128 * SG_PITCH)
#define SG_OFF_STAGE (2 * SG_TILE)          // E staging reuses K region
#define SG_EPITCH 272                        // fp16 row pitch (bytes), 16-aligned
#define SG_OFF_MASK (4 * SG_TILE)
#define SG_OFF_MAX  (SG_OFF_MASK + 512)
#define SG_OFF_SUM  (SG_OFF_MAX + 1024)
#define SG_SMEM     (SG_OFF_SUM + 1024)

__global__ __launch_bounds__(256, 2) void attn_sgemm(
    const __nv_bfloat16* __restrict__ Qh, const __nv_bfloat16* __restrict__ Ql,
    const __nv_bfloat16* __restrict__ Kh, const __nv_bfloat16* __restrict__ Kl,
    const int* __restrict__ mask,
    __half* __restrict__ E,
    float* __restrict__ pmax, float* __restrict__ psum)
{
    extern __shared__ char smem[];
    uint32_t sb = smem_to_u32(smem);
    const int tid = threadIdx.x;
    const int lane = tid & 31;
    const int wid = tid >> 5;
    const int wm = wid >> 1;
    const int wn = wid & 1;
    const int h  = blockIdx.z;
    const int kb = blockIdx.x * 128;
    const int qb = blockIdx.y * 128;

    auto load_tile = [&](int tt, const __nv_bfloat16* src, int grow0) {
#pragma unroll
        for (int j = 0; j < 4; ++j) {
            int idx = tid + j * 256;
            int r = idx >> 3, c = idx & 7;
            uint32_t sm = sb + (uint32_t)(tt * SG_TILE + r * SG_PITCH + c * 16);
            CP_ASYNC16(sm, src + (size_t)(grow0 + r) * DM + h * DKH + c * 8);
        }
    };

    load_tile(0, Qh, qb);
    load_tile(2, Kh, kb);
    CP_COMMIT();
    load_tile(1, Ql, qb);
    load_tile(3, Kl, kb);
    CP_COMMIT();
    int* sMask = (int*)(smem + SG_OFF_MASK);
    if (tid < 128) sMask[tid] = mask[kb + tid];

    float acc[2][8][4];
#pragma unroll
    for (int i = 0; i < 2; ++i)
#pragma unroll
        for (int j = 0; j < 8; ++j)
#pragma unroll
            for (int c = 0; c < 4; ++c) acc[i][j][c] = 0.f;

    const uint32_t aH = sb, aL = sb + SG_TILE, bH = sb + 2 * SG_TILE, bL = sb + 3 * SG_TILE;
    const int brow = (lane & 7) + ((lane >> 4) << 3);

    CP_WAIT1();
    __syncthreads();

    // term 1: Ah x Bh
#pragma unroll
    for (int ks = 0; ks < 4; ++ks) {
        uint32_t aoff = (uint32_t)((wm * 32 + (lane & 15)) * SG_PITCH + ks * 32 + (lane >> 4) * 16);
        uint32_t ah0[4], ah1[4];
        LDSM_X4(ah0[0], ah0[1], ah0[2], ah0[3], aH + aoff);
        LDSM_X4(ah1[0], ah1[1], ah1[2], ah1[3], aH + aoff + 16 * SG_PITCH);
        uint32_t bko = (uint32_t)(ks * 32 + ((lane >> 3) & 1) * 16);
#pragma unroll
        for (int p = 0; p < 4; ++p) {
            uint32_t boff = (uint32_t)((wn * 64 + p * 16 + brow) * SG_PITCH) + bko;
            uint32_t b0, b1, b2, b3;
            LDSM_X4(b0, b1, b2, b3, bH + boff);
            MMA16816(acc[0][2 * p],     ah0, b0, b1);
            MMA16816(acc[0][2 * p + 1], ah0, b2, b3);
            MMA16816(acc[1][2 * p],     ah1, b0, b1);
            MMA16816(acc[1][2 * p + 1], ah1, b2, b3);
        }
    }

    CP_WAIT0();
    __syncthreads();

    // terms 2+3: Ah x Bl, Al x Bh
#pragma unroll
    for (int ks = 0; ks < 4; ++ks) {
        uint32_t aoff = (uint32_t)((wm * 32 + (lane & 15)) * SG_PITCH + ks * 32 + (lane >> 4) * 16);
        uint32_t ah0[4], ah1[4], al0[4], al1[4];
        LDSM_X4(ah0[0], ah0[1], ah0[2], ah0[3], aH + aoff);
        LDSM_X4(ah1[0], ah1[1], ah1[2], ah1[3], aH + aoff + 16 * SG_PITCH);
        LDSM_X4(al0[0], al0[1], al0[2], al0[3], aL + aoff);
        LDSM_X4(al1[0], al1[1], al1[2], al1[3], aL + aoff + 16 * SG_PITCH);
        uint32_t bko = (uint32_t)(ks * 32 + ((lane >> 3) & 1) * 16);
#pragma unroll
        for (int p = 0; p < 4; ++p) {
            uint32_t boff = (uint32_t)((wn * 64 + p * 16 + brow) * SG_PITCH) + bko;
            uint32_t bh0, bh1, bh2, bh3, bl0, bl1, bl2, bl3;
            LDSM_X4(bh0, bh1, bh2, bh3, bH + boff);
            LDSM_X4(bl0, bl1, bl2, bl3, bL + boff);
            MMA16816(acc[0][2 * p],     ah0, bl0, bl1);
            MMA16816(acc[0][2 * p + 1], ah0, bl2, bl3);
            MMA16816(acc[1][2 * p],     ah1, bl0, bl1);
            MMA16816(acc[1][2 * p + 1], ah1, bl2, bl3);
            MMA16816(acc[0][2 * p],     al0, bh0, bh1);
            MMA16816(acc[0][2 * p + 1], al0, bh2, bh3);
            MMA16816(acc[1][2 * p],     al1, bh0, bh1);
            MMA16816(acc[1][2 * p + 1], al1, bh2, bh3);
        }
    }

    // ---- epilogue: scale+mask, tile max, exp+stats, STAGED E store ----
    const int c0 = (lane & 3) * 2;
    const int r0 = lane >> 2;
#pragma unroll
    for (int mf = 0; mf < 2; ++mf)
#pragma unroll
        for (int nf = 0; nf < 8; ++nf) {
            int col = wn * 64 + nf * 8 + c0;
            bool k0 = sMask[col] != 0, k1 = sMask[col + 1] != 0;
            acc[mf][nf][0] = k0 ? acc[mf][nf][0] * 0.125f : -1e9f;
            acc[mf][nf][1] = k1 ? acc[mf][nf][1] * 0.125f : -1e9f;
            acc[mf][nf][2] = k0 ? acc[mf][nf][2] * 0.125f : -1e9f;
            acc[mf][nf][3] = k1 ? acc[mf][nf][3] * 0.125f : -1e9f;
        }

    float* sMax = (float*)(smem + SG_OFF_MAX);
    float* sSum = (float*)(smem + SG_OFF_SUM);
    float rmax[2][2];
#pragma unroll
    for (int mf = 0; mf < 2; ++mf)
#pragma unroll
        for (int hf = 0; hf < 2; ++hf) {
            float m = -INFINITY;
#pragma unroll
            for (int nf = 0; nf < 8; ++nf) {
                m = fmaxf(m, acc[mf][nf][hf * 2]);
                m = fmaxf(m, acc[mf][nf][hf * 2 + 1]);
            }
            m = fmaxf(m, __shfl_xor_sync(0xffffffffu, m, 1));
            m = fmaxf(m, __shfl_xor_sync(0xffffffffu, m, 2));
            if ((lane & 3) == 0) sMax[(wm * 32 + mf * 16 + hf * 8 + r0) * 2 + wn] = m;
        }
    __syncthreads();
#pragma unroll
    for (int mf = 0; mf < 2; ++mf)
#pragma unroll
        for (int hf = 0; hf < 2; ++hf) {
            int row = wm * 32 + mf * 16 + hf * 8 + r0;
            float M = fmaxf(sMax[row * 2], sMax[row * 2 + 1]);
            rmax[mf][hf] = M;
            float s = 0.f;
#pragma unroll
            for (int nf = 0; nf < 8; ++nf) {
                float e0 = __expf(acc[mf][nf][hf * 2]     - M);
                float e1 = __expf(acc[mf][nf][hf * 2 + 1] - M);
                acc[mf][nf][hf * 2]     = e0;
                acc[mf][nf][hf * 2 + 1] = e1;
                s += e0 + e1;
            }
            s += __shfl_xor_sync(0xffffffffu, s, 1);
            s += __shfl_xor_sync(0xffffffffu, s, 2);
            if ((lane & 3) == 0) sSum[row * 2 + wn] = s;
        }
    __syncthreads();   // all mma reads of bH/bL done -> staging region safe to reuse
    if (wn == 0 && (lane & 3) == 0) {
#pragma unroll
        for (int mf = 0; mf < 2; ++mf)
#pragma unroll
            for (int hf = 0; hf < 2; ++hf) {
                int row = wm * 32 + mf * 16 + hf * 8 + r0;
                size_t sidx = (size_t)(h * 16 + blockIdx.x) * SEQ + qb + row;
                pmax[sidx] = rmax[mf][hf];
                psum[sidx] = sSum[row * 2] + sSum[row * 2 + 1];
            }
    }

    // stage E tile in smem (fragment layout STS, conflict-free at pitch 272)
    char* sE = smem + SG_OFF_STAGE;
#pragma unroll
    for (int mf = 0; mf < 2; ++mf)
#pragma unroll
        for (int hf = 0; hf < 2; ++hf) {
            int row = wm * 32 + mf * 16 + hf * 8 + r0;
#pragma unroll
            for (int nf = 0; nf < 8; ++nf) {
                int col = wn * 64 + nf * 8 + c0;
                *(__half2*)(sE + row * SG_EPITCH + col * 2) =
                    __floats2half2_rn(acc[mf][nf][hf * 2], acc[mf][nf][hf * 2 + 1]);
            }
        }
    __syncthreads();

    // coalesced flush: 2048 uint4 chunks, 8 per thread, 256B per row segment
#pragma unroll
    for (int j = 0; j < 8; ++j) {
        int idx = tid + j * 256;
        int row = idx >> 4, c = idx & 15;
        uint4 val = *(const uint4*)(sE + row * SG_EPITCH + c * 16);
        *(uint4*)&E[((size_t)h * SEQ + qb + row) * SEQ + kb + c * 8] = val;
    }
}

// ===========================================================================
// attn_pv2: K-chunk 64 (R12, validated). mma on RAW E into per-iter partial,
// fold acc += c*p; attn emitted straight from E smem. Split bf16 ctx out.
// ===========================================================================
#define PA_TILE (128 * 144)
#define PB_TILE (64 * 144)
#define PV_STAGE (PA_TILE + 2 * PB_TILE)
#define PV_OFF_ST (2 * PV_STAGE)
#define PV_SMEM (PV_OFF_ST + 16 * 128 * 4)

__global__ __launch_bounds__(256, 2) void attn_pv2(
    const __half* __restrict__ E,
    const __half* __restrict__ Vh, const __half* __restrict__ Vl,
    const float* __restrict__ pmax, const float* __restrict__ psum,
    float* __restrict__ attn,
    __nv_bfloat16* __restrict__ Ch, __nv_bfloat16* __restrict__ Cl)
{
    extern __shared__ char smem[];
    uint32_t sb = smem_to_u32(smem);

    const int tid  = threadIdx.x;
    const int lane = tid & 31;
    const int wid  = tid >> 5;
    const int wm   = wid >> 1;
    const int wn   = wid & 1;
    const int h    = blockIdx.y;
    const int bm   = blockIdx.x * 128;

    float acc[2][4][4];
#pragma unroll
    for (int i = 0; i < 2; ++i)
#pragma unroll
        for (int j = 0; j < 4; ++j)
#pragma unroll
            for (int c = 0; c < 4; ++c) acc[i][j][c] = 0.f;

    auto issue_stage = [&](int it, int s) {
#pragma unroll
        for (int j = 0; j < 8; ++j) {
            int c2 = tid + j * 256;
            uint32_t sm;
            const __half* g8;
            if (c2 < 1024) {
                int r = c2 >> 3, c = c2 & 7;
                sm = sb + (uint32_t)(s * PV_STAGE + r * 144 + c * 16);
                g8 = E + ((size_t)h * SEQ + bm + r) * SEQ + it * 64 + c * 8;
            } else {
                int c2b = c2 - 1024;
                int mat = c2b >> 9;
                int idx = c2b & 511;
                int r = idx >> 3, c = idx & 7;
                sm = sb + (uint32_t)(s * PV_STAGE + PA_TILE + mat * PB_TILE + r * 144 + c * 16);
                g8 = (mat ? Vl : Vh) + (size_t)(it * 64 + r) * DM + h * DKH + c * 8;
            }
            CP_ASYNC16(sm, g8);
        }
        CP_COMMIT();
    };

    issue_stage(0, 0);

    float* sC = (float*)(smem + PV_OFF_ST);
    if (tid < 128) {
        int qrow = bm + tid;
        float pm[16];
        float M = -INFINITY;
#pragma unroll
        for (int kt = 0; kt < 16; ++kt) {
            pm[kt] = pmax[(size_t)(h * 16 + kt) * SEQ + qrow];
            M = fmaxf(M, pm[kt]);
        }
        float S = 0.f;
#pragma unroll
        for (int kt = 0; kt < 16; ++kt)
            S += psum[(size_t)(h * 16 + kt) * SEQ + qrow] * __expf(pm[kt] - M);
        float inv = 1.0f / S;
#pragma unroll
        for (int kt = 0; kt < 16; ++kt)
            sC[kt * 128 + tid] = __expf(pm[kt] - M) * inv;
    }

    const int l4 = lane >> 2;

    for (int it = 0; it < SEQ / 64; ++it) {
        const int s = it & 1;
        if (it + 1 < SEQ / 64) { issue_stage(it + 1, s ^ 1); CP_WAIT1(); }
        else                   { CP_WAIT0(); }
        __syncthreads();

        const uint32_t aEb = sb + s * PV_STAGE;
        const uint32_t vHb = aEb + PA_TILE;
        const uint32_t vLb = vHb + PB_TILE;
        const float* cRow = &sC[(it >> 1) * 128];

        float accP[2][4][4];
#pragma unroll
        for (int i = 0; i < 2; ++i)
#pragma unroll
            for (int j = 0; j < 4; ++j)
#pragma unroll
                for (int c = 0; c < 4; ++c) accP[i][j][c] = 0.f;

#pragma unroll
        for (int ks = 0; ks < 4; ++ks) {
            uint32_t aoff = (uint32_t)((wm * 32 + (lane & 15)) * 144 + ks * 32 + (lane >> 4) * 16);
            uint32_t e0[4], e1[4];
            LDSM_X4(e0[0], e0[1], e0[2], e0[3], aEb + aoff);
            LDSM_X4(e1[0], e1[1], e1[2], e1[3], aEb + aoff + 16 * 144);

            const int vrow = ks * 16 + ((lane >> 3) & 1) * 8 + (lane & 7);
            uint32_t bh[2][4], bl[2][4];
#pragma unroll
            for (int p = 0; p < 2; ++p) {
                int vcol = wn * 32 + p * 16 + ((lane >> 4) & 1) * 8;
                uint32_t voff = (uint32_t)(vrow * 144 + vcol * 2);
                LDSM_X4T(bh[p][0], bh[p][1], bh[p][2], bh[p][3], vHb + voff);
                LDSM_X4T(bl[p][0], bl[p][1], bl[p][2], bl[p][3], vLb + voff);
            }
#pragma unroll
            for (int mf = 0; mf < 2; ++mf) {
                const uint32_t* A_ = mf ? e1 : e0;
#pragma unroll
                for (int p = 0; p < 2; ++p) {
                    MMA16816H(accP[mf][2 * p],     A_, bh[p][0], bh[p][1]);
                    MMA16816H(accP[mf][2 * p + 1], A_, bh[p][2], bh[p][3]);
                    MMA16816H(accP[mf][2 * p],     A_, bl[p][0], bl[p][1]);
                    MMA16816H(accP[mf][2 * p + 1], A_, bl[p][2], bl[p][3]);
                }
            }
        }

#pragma unroll
        for (int mf = 0; mf < 2; ++mf) {
            float cv0 = cRow[wm * 32 + mf * 16 + l4];
            float cv1 = cRow[wm * 32 + mf * 16 + 8 + l4];
#pragma unroll
            for (int nf = 0; nf < 4; ++nf) {
                acc[mf][nf][0] += cv0 * accP[mf][nf][0];
                acc[mf][nf][1] += cv0 * accP[mf][nf][1];
                acc[mf][nf][2] += cv1 * accP[mf][nf][2];
                acc[mf][nf][3] += cv1 * accP[mf][nf][3];
            }
        }

        {
            const char* pa = smem + s * PV_STAGE;
#pragma unroll
            for (int j = 0; j < 4; ++j) {
                int idx = tid + j * 256;
                int r = idx >> 3, c = idx & 7;
                uint4 ue = *(const uint4*)(pa + r * 144 + c * 16);
                const __half2* eb = (const __half2*)&ue;
                float cv = cRow[r];
                float p[8];
#pragma unroll
                for (int e = 0; e < 4; ++e) {
                    p[2 * e]     = __low2float(eb[e])  * cv;
                    p[2 * e + 1] = __high2float(eb[e]) * cv;
                }
                float* ga = attn + ((size_t)h * SEQ + bm + r) * SEQ + it * 64 + c * 8;
                *(float4*)ga       = make_float4(p[0], p[1], p[2], p[3]);
                *(float4*)(ga + 4) = make_float4(p[4], p[5], p[6], p[7]);
            }
        }
        __syncthreads();
    }

    const int l2 = (lane & 3) * 2;
#pragma unroll
    for (int mf = 0; mf < 2; ++mf) {
        int q = bm + wm * 32 + mf * 16 + l4;
#pragma unroll
        for (int nf = 0; nf < 4; ++nf) {
            int col = h * DKH + wn * 32 + nf * 8 + l2;
            __nv_bfloat16 h0, h1, l0, l1;
            split2(acc[mf][nf][0], h0, l0);
            split2(acc[mf][nf][1], h1, l1);
            *(__nv_bfloat162*)&Ch[(size_t)q * DM + col] = __nv_bfloat162(h0, h1);
            *(__nv_bfloat162*)&Cl[(size_t)q * DM + col] = __nv_bfloat162(l0, l1);
            split2(acc[mf][nf][2], h0, l0);
            split2(acc[mf][nf][3], h1, l1);
            *(__nv_bfloat162*)&Ch[(size_t)(q + 8) * DM + col] = __nv_bfloat162(h0, h1);
            *(__nv_bfloat162*)&Cl[(size_t)(q + 8) * DM + col] = __nv_bfloat162(l0, l1);
        }
    }
}

// ===========================================================================
extern "C" void kernel_launch(void* const* d_in, const int* in_sizes, int n_in,
                              void* d_out, int out_size)
{
    const float* q    = (const float*)d_in[0];
    const float* k    = (const float*)d_in[1];
    const float* v    = (const float*)d_in[2];
    const int*   mask = (const int*)  d_in[3];
    const float* Wq   = (const float*)d_in[4];
    const float* bq   = (const float*)d_in[5];
    const float* Wk   = (const float*)d_in[6];
    const float* bk   = (const float*)d_in[7];
    const float* Wv   = (const float*)d_in[8];
    const float* bv   = (const float*)d_in[9];
    const float* Wo   = (const float*)d_in[10];
    const float* bo   = (const float*)d_in[11];

    float *Qp, *Kp, *Vp, *Ap, *Op, *pmaxp, *psump;
    cudaGetSymbolAddress((void**)&Qp, g_Q);
    cudaGetSymbolAddress((void**)&Kp, g_K);
    cudaGetSymbolAddress((void**)&Vp, g_V);
    cudaGetSymbolAddress((void**)&Ap, g_ATTN);
    cudaGetSymbolAddress((void**)&Op, g_OUT);
    cudaGetSymbolAddress((void**)&pmaxp, g_pmax);
    cudaGetSymbolAddress((void**)&psump, g_psum);

    __nv_bfloat16 *qh, *ql, *kh, *kl, *vh, *vl, *ch, *cl;
    __nv_bfloat16 *Wqh, *Wql, *Wkh, *Wkl, *Wvh, *Wvl, *Woh, *Wol;
    __half* Ep;
    cudaGetSymbolAddress((void**)&qh, g_qh);   cudaGetSymbolAddress((void**)&ql, g_ql);
    cudaGetSymbolAddress((void**)&kh, g_kh);   cudaGetSymbolAddress((void**)&kl, g_kl);
    cudaGetSymbolAddress((void**)&vh, g_vh);   cudaGetSymbolAddress((void**)&vl, g_vl);
    cudaGetSymbolAddress((void**)&ch, g_ch);   cudaGetSymbolAddress((void**)&cl, g_cl);
    cudaGetSymbolAddress((void**)&Ep, g_E);
    cudaGetSymbolAddress((void**)&Wqh, g_Wqh); cudaGetSymbolAddress((void**)&Wql, g_Wql);
    cudaGetSymbolAddress((void**)&Wkh, g_Wkh); cudaGetSymbolAddress((void**)&Wkl, g_Wkl);
    cudaGetSymbolAddress((void**)&Wvh, g_Wvh); cudaGetSymbolAddress((void**)&Wvl, g_Wvl);
    cudaGetSymbolAddress((void**)&Woh, g_Woh); cudaGetSymbolAddress((void**)&Wol, g_Wol);

    __nv_bfloat16* pqh = (__nv_bfloat16*)Qp; __nv_bfloat16* pql = pqh + (size_t)SEQ * DM;
    __nv_bfloat16* pkh = (__nv_bfloat16*)Kp; __nv_bfloat16* pkl = pkh + (size_t)SEQ * DM;
    __half* pvh = (__half*)Vp; __half* pvl = pvh + (size_t)SEQ * DM;

    const size_t OUT_ELEMS  = (size_t)SEQ * DM;
    const size_t ATTN_ELEMS = (size_t)NH * SEQ * SEQ;

    float* outp = (float*)d_out;
    float* attnp;
    if ((size_t)out_size >= OUT_ELEMS + ATTN_ELEMS) {
        attnp = outp + OUT_ELEMS;
    } else if ((size_t)out_size == ATTN_ELEMS) {
        attnp = (float*)d_out;
        outp  = Op;
    } else {
        attnp = Ap;
    }

    cudaFuncSetAttribute(gemm_mma,
                         cudaFuncAttributeMaxDynamicSharedMemorySize, GEMM_SMEM);
    cudaFuncSetAttribute(attn_sgemm,
                         cudaFuncAttributeMaxDynamicSharedMemorySize, SG_SMEM);
    cudaFuncSetAttribute(attn_pv2,
                         cudaFuncAttributeMaxDynamicSharedMemorySize, PV_SMEM);

    // 1) split inputs + weights
    {
        PrepBatch pb;
        pb.src[0] = q;  pb.hi[0] = qh;  pb.lo[0] = ql;  pb.n4[0] = SEQ * DM / 4;
        pb.src[1] = k;  pb.hi[1] = kh;  pb.lo[1] = kl;  pb.n4[1] = SEQ * DM / 4;
        pb.src[2] = v;  pb.hi[2] = vh;  pb.lo[2] = vl;  pb.n4[2] = SEQ * DM / 4;
        pb.src[3] = Wq; pb.hi[3] = Wqh; pb.lo[3] = Wql; pb.n4[3] = DM * DM / 4;
        pb.src[4] = Wk; pb.hi[4] = Wkh; pb.lo[4] = Wkl; pb.n4[4] = DM * DM / 4;
        pb.src[5] = Wv; pb.hi[5] = Wvh; pb.lo[5] = Wvl; pb.n4[5] = DM * DM / 4;
        pb.src[6] = Wo; pb.hi[6] = Woh; pb.lo[6] = Wol; pb.n4[6] = DM * DM / 4;
        pb.src[7] = q;  pb.hi[7] = qh;  pb.lo[7] = ql;  pb.n4[7] = 0;
        dim3 pg((SEQ * DM / 4 + 255) / 256, 1, 7);
        split_prep<<<pg, 256>>>(pb);
    }

    // 2) Q/K/V projections -> Q,K bf16 split; V fp16 split
    {
        GemmBatch gb;
        gb.g[0] = { qh, ql, Wqh, Wql, bq, nullptr, pqh, pql, nullptr, nullptr };
        gb.g[1] = { kh, kl, Wkh, Wkl, bk, nullptr, pkh, pkl, nullptr, nullptr };
        gb.g[2] = { vh, vl, Wvh, Wvl, bv, nullptr, nullptr, nullptr, pvh, pvl };
        gemm_mma<<<dim3(DM / 128, SEQ / 128, 3), 256, GEMM_SMEM>>>(gb);
    }

    // 3) scores GEMM -> fp16 exp(S - m_tile) (staged coalesced store) + stats
    attn_sgemm<<<dim3(SEQ / 128, SEQ / 128, NH), 256, SG_SMEM>>>(
        pqh, pql, pkh, pkl, mask, Ep, pmaxp, psump);

    // 4) fused rescale + attn-emit + P@V (fp16 mma, deferred scaling) -> split ctx
    attn_pv2<<<dim3(SEQ / 128, NH), 256, PV_SMEM>>>(
        Ep, pvh, pvl, pmaxp, psump, attnp, ch, cl);

    // 5) output projection (fp32 out)
    {
        GemmBatch gb;
        gb.g[0] = { ch, cl, Woh, Wol, bo, outp, nullptr, nullptr, nullptr, nullptr };
        gb.g[1] = gb.g[0];
        gb.g[2] = gb.g[0];
        gemm_mma<<<dim3(DM / 128, SEQ / 128, 1), 256, GEMM_SMEM>>>(gb);
    }
}